// round 1
// baseline (speedup 1.0000x reference)
#include <cuda_runtime.h>

// Problem constants
constexpr int CB = 8;     // batch
constexpr int CS = 2048;  // seq len
constexpr int CD = 1024;  // model dim
constexpr int CU = 1024;  // units

constexpr size_t QKV_ELEMS = (size_t)CB * CS * CU;  // 16M floats
constexpr size_t P_ELEMS   = (size_t)CB * CS * CS;  // 33.5M floats

// Scratch (allocation-free rule: __device__ globals)
__device__ float g_Q[QKV_ELEMS];
__device__ float g_K[QKV_ELEMS];
__device__ float g_V[QKV_ELEMS];
__device__ float g_P[P_ELEMS];

#define BM 128
#define BN 128
#define BK 8

// Classic 128x128x8 register-tiled SGEMM, 256 threads, 8x8 microtile per thread.
// TRANS_B == 0:  C[m,n] = alpha * sum_k A[m,k] * B[k,n]   (B row-major KxN)
// TRANS_B == 1:  C[m,n] = alpha * sum_k A[m,k] * B[n,k]   (B row-major NxK)
// blockIdx.z batches with strides sA/sB/sC.
template <int TRANS_B>
__global__ void __launch_bounds__(256, 2) sgemm_kernel(
    const float* __restrict__ Ag, const float* __restrict__ Bg,
    float* __restrict__ Cg, int M, int N, int K,
    size_t sA, size_t sB, size_t sC, float alpha)
{
    const float* A = Ag + (size_t)blockIdx.z * sA;
    const float* Bp = Bg + (size_t)blockIdx.z * sB;
    float* C = Cg + (size_t)blockIdx.z * sC;

    __shared__ float As[BK][BM];
    __shared__ float Bs[BK][BN];

    const int tid = threadIdx.x;
    const int m0 = blockIdx.y * BM;
    const int n0 = blockIdx.x * BN;

    // Global->shared load mapping (transposed store for A and NT-B):
    const int ldr = tid >> 1;         // 0..127 : row within 128-row tile
    const int ldc = (tid & 1) * 4;    // 0 or 4 : col (K) offset
    // NN-B load mapping:
    const int bnr = tid >> 5;         // 0..7
    const int bnc = (tid & 31) * 4;   // 0..124

    // Compute fragment bases: two 4-wide groups separated by 64 (bank-friendly)
    const int rr = (tid >> 4) * 4;    // 0..60
    const int cc = (tid & 15) * 4;    // 0..60

    float acc[8][8];
#pragma unroll
    for (int i = 0; i < 8; i++)
#pragma unroll
        for (int j = 0; j < 8; j++) acc[i][j] = 0.f;

    for (int k0 = 0; k0 < K; k0 += BK) {
        float4 av = *(const float4*)(A + (size_t)(m0 + ldr) * K + (k0 + ldc));
        As[ldc + 0][ldr] = av.x;
        As[ldc + 1][ldr] = av.y;
        As[ldc + 2][ldr] = av.z;
        As[ldc + 3][ldr] = av.w;

        if (TRANS_B) {
            float4 bv = *(const float4*)(Bp + (size_t)(n0 + ldr) * K + (k0 + ldc));
            Bs[ldc + 0][ldr] = bv.x;
            Bs[ldc + 1][ldr] = bv.y;
            Bs[ldc + 2][ldr] = bv.z;
            Bs[ldc + 3][ldr] = bv.w;
        } else {
            *(float4*)(&Bs[bnr][bnc]) =
                *(const float4*)(Bp + (size_t)(k0 + bnr) * N + (n0 + bnc));
        }
        __syncthreads();

#pragma unroll
        for (int kk = 0; kk < BK; kk++) {
            float a[8], b[8];
            *(float4*)&a[0] = *(const float4*)&As[kk][rr];
            *(float4*)&a[4] = *(const float4*)&As[kk][rr + 64];
            *(float4*)&b[0] = *(const float4*)&Bs[kk][cc];
            *(float4*)&b[4] = *(const float4*)&Bs[kk][cc + 64];
#pragma unroll
            for (int i = 0; i < 8; i++)
#pragma unroll
                for (int j = 0; j < 8; j++) acc[i][j] += a[i] * b[j];
        }
        __syncthreads();
    }

#pragma unroll
    for (int i = 0; i < 8; i++) {
        int row = m0 + ((i < 4) ? (rr + i) : (64 + rr + (i - 4)));
        float4 v0 = make_float4(acc[i][0] * alpha, acc[i][1] * alpha,
                                acc[i][2] * alpha, acc[i][3] * alpha);
        float4 v1 = make_float4(acc[i][4] * alpha, acc[i][5] * alpha,
                                acc[i][6] * alpha, acc[i][7] * alpha);
        *(float4*)(C + (size_t)row * N + (n0 + cc)) = v0;
        *(float4*)(C + (size_t)row * N + (n0 + cc + 64)) = v1;
    }
}

// Row softmax over 2048 columns; one block (256 threads) per row,
// row held in registers (8 floats/thread) -> one read + one write of P.
__global__ void __launch_bounds__(256) softmax2048(float* __restrict__ P)
{
    float* row = P + (size_t)blockIdx.x * 2048;
    const int tid = threadIdx.x;
    __shared__ float red[32];
    __shared__ float bcast;

    float v[8];
#pragma unroll
    for (int i = 0; i < 8; i++) v[i] = row[tid + 256 * i];

    float mx = v[0];
#pragma unroll
    for (int i = 1; i < 8; i++) mx = fmaxf(mx, v[i]);
#pragma unroll
    for (int o = 16; o; o >>= 1) mx = fmaxf(mx, __shfl_xor_sync(0xffffffffu, mx, o));
    if ((tid & 31) == 0) red[tid >> 5] = mx;
    __syncthreads();
    if (tid < 32) {
        float t = (tid < 8) ? red[tid] : -3.4e38f;
#pragma unroll
        for (int o = 4; o; o >>= 1) t = fmaxf(t, __shfl_xor_sync(0xffffffffu, t, o));
        if (tid == 0) bcast = t;
    }
    __syncthreads();
    mx = bcast;

    float sum = 0.f;
#pragma unroll
    for (int i = 0; i < 8; i++) {
        v[i] = __expf(v[i] - mx);
        sum += v[i];
    }
#pragma unroll
    for (int o = 16; o; o >>= 1) sum += __shfl_xor_sync(0xffffffffu, sum, o);
    __syncthreads();  // red[] reuse safety
    if ((tid & 31) == 0) red[tid >> 5] = sum;
    __syncthreads();
    if (tid < 32) {
        float t = (tid < 8) ? red[tid] : 0.f;
#pragma unroll
        for (int o = 4; o; o >>= 1) t += __shfl_xor_sync(0xffffffffu, t, o);
        if (tid == 0) bcast = t;
    }
    __syncthreads();

    float inv = 1.0f / bcast;
#pragma unroll
    for (int i = 0; i < 8; i++) row[tid + 256 * i] = v[i] * inv;
}

extern "C" void kernel_launch(void* const* d_in, const int* in_sizes, int n_in,
                              void* d_out, int out_size)
{
    const float* X  = (const float*)d_in[0];
    const float* Wq = (const float*)d_in[1];
    const float* Wk = (const float*)d_in[2];
    const float* Wv = (const float*)d_in[3];
    float* out = (float*)d_out;

    float *qp, *kp, *vp, *pp;
    cudaGetSymbolAddress((void**)&qp, g_Q);
    cudaGetSymbolAddress((void**)&kp, g_K);
    cudaGetSymbolAddress((void**)&vp, g_V);
    cudaGetSymbolAddress((void**)&pp, g_P);

    dim3 blk(256);

    // QKV projections: [16384,1024] x [1024,1024], NN
    dim3 g1(CU / BN, (CB * CS) / BM, 1);  // (8, 128)
    sgemm_kernel<0><<<g1, blk>>>(X, Wq, qp, CB * CS, CU, CD, 0, 0, 0, 1.0f);
    sgemm_kernel<0><<<g1, blk>>>(X, Wk, kp, CB * CS, CU, CD, 0, 0, 0, 1.0f);
    sgemm_kernel<0><<<g1, blk>>>(X, Wv, vp, CB * CS, CU, CD, 0, 0, 0, 1.0f);

    // scores = Q @ K^T / sqrt(U), batched NT
    dim3 g2(CS / BN, CS / BM, CB);  // (16, 16, 8)
    sgemm_kernel<1><<<g2, blk>>>(qp, kp, pp, CS, CS, CU,
                                 (size_t)CS * CU, (size_t)CS * CU,
                                 (size_t)CS * CS, 1.0f / 32.0f);

    // softmax over last dim
    softmax2048<<<CB * CS, 256>>>(pp);

    // out = P @ V, batched NN
    dim3 g3(CU / BN, CS / BM, CB);  // (8, 16, 8)
    sgemm_kernel<0><<<g3, blk>>>(pp, vp, out, CS, CU, CS,
                                 (size_t)CS * CS, (size_t)CS * CU,
                                 (size_t)CS * CU, 1.0f);
}

// round 3
// speedup vs baseline: 2.1943x; 2.1943x over previous
#include <cuda_runtime.h>
#include <cuda_bf16.h>
#include <cstdint>

// ============================================================
// B=8, S=2048, D=1024, U=1024 fp32 self-attention.
// Error-compensated bf16 split (hi+lo), 3-phase K concat:
//   a*b ~= a_hi*b_hi + a_hi*b_lo + a_lo*b_hi, K' = 3K.
// GEMM core: sm_80-class mma.sync m16n8k16 + cp.async pipeline
// (tcgen05 unavailable: harness PTX targets sm_103, not sm_103a).
// ============================================================

constexpr int CB = 8, CS = 2048;
constexpr int MR = CB * CS;   // 16384 rows, batch folded

// -------- scratch (__device__ globals; no allocation allowed) --------
__device__ __align__(1024) __nv_bfloat16 g_Xs [(size_t)MR * 2048];
__device__ __align__(1024) __nv_bfloat16 g_Wqs[(size_t)1024 * 2048];
__device__ __align__(1024) __nv_bfloat16 g_Wks[(size_t)1024 * 2048];
__device__ __align__(1024) __nv_bfloat16 g_Wvs[(size_t)1024 * 2048];
__device__ __align__(1024) __nv_bfloat16 g_Qs [(size_t)MR * 2048];
__device__ __align__(1024) __nv_bfloat16 g_Ks [(size_t)MR * 2048];
__device__ __align__(1024) float         g_Vf [(size_t)MR * 1024];
__device__ __align__(1024) __nv_bfloat16 g_Vts[(size_t)CB * 1024 * 4096];
__device__ __align__(1024) float         g_P  [(size_t)MR * 2048];
__device__ __align__(1024) __nv_bfloat16 g_Ps [(size_t)MR * 4096];

// ======================= asm helpers (all sm_80-level) =======================
__device__ __forceinline__ uint32_t smem_u32(const void* p) {
    uint32_t a;
    asm("{ .reg .u64 t; cvta.to.shared.u64 t, %1; cvt.u32.u64 %0, t; }"
        : "=r"(a) : "l"(p));
    return a;
}
__device__ __forceinline__ void cp16(uint32_t sp, const void* gp) {
    asm volatile("cp.async.cg.shared.global [%0], [%1], 16;"
                 :: "r"(sp), "l"(gp) : "memory");
}
__device__ __forceinline__ void ldm4(uint32_t* r, uint32_t a) {
    asm volatile("ldmatrix.sync.aligned.m8n8.x4.shared.b16 {%0,%1,%2,%3}, [%4];"
                 : "=r"(r[0]), "=r"(r[1]), "=r"(r[2]), "=r"(r[3]) : "r"(a));
}
__device__ __forceinline__ void mma16816(float* c, const uint32_t* a, const uint32_t* b) {
    asm volatile(
        "mma.sync.aligned.m16n8k16.row.col.f32.bf16.bf16.f32 "
        "{%0,%1,%2,%3},{%4,%5,%6,%7},{%8,%9},{%0,%1,%2,%3};"
        : "+f"(c[0]), "+f"(c[1]), "+f"(c[2]), "+f"(c[3])
        : "r"(a[0]), "r"(a[1]), "r"(a[2]), "r"(a[3]), "r"(b[0]), "r"(b[1]));
}

// ======================= GEMM kernel =======================
// C[128,128] tile of C = A[M,K'] * B[N,K']^T, A/B bf16 K-major.
// K' = 3 phases over segments of width Kseg (kc = Kseg/64 chunks/phase):
//   A col offset: phase2 -> +Kseg (lo);  B col offset: phase1 -> +Kseg (lo).
// 3-stage cp.async pipeline, BK=64 (128B smem rows, xor-swizzled).
constexpr int ST_BYTES = 128 * 128 * 2;        // 32KB per stage (A 16K + B 16K)
constexpr int SMEM_SZ  = 3 * ST_BYTES;         // 96KB

template <int EPI>   // 0: fp32 out (alpha), 1: split bf16 hi|lo out
__global__ void __launch_bounds__(256, 1) gemm_hmma(
    const __nv_bfloat16* __restrict__ A, const __nv_bfloat16* __restrict__ B,
    float* __restrict__ Cf, __nv_bfloat16* __restrict__ Cs,
    int lda, int ldb, int ldc, int Kseg, int kc, int nchunks,
    float alpha, int m_per_batch, int nb_rows)
{
    extern __shared__ __align__(1024) char smem[];
    const uint32_t sbase = smem_u32(smem);
    const int tid = threadIdx.x, wid = tid >> 5, lane = tid & 31;
    const int m0 = blockIdx.y * 128;
    const int n0 = blockIdx.x * 128;
    const int batch = m0 / m_per_batch;
    const int brow0 = batch * nb_rows + n0;

    const int wm = (wid & 1) * 64;   // warp M offset (2 x 64)
    const int wn = (wid >> 1) * 32;  // warp N offset (4 x 32)

    float acc[4][4][4];
#pragma unroll
    for (int i = 0; i < 4; i++)
#pragma unroll
        for (int j = 0; j < 4; j++)
#pragma unroll
            for (int t = 0; t < 4; t++) acc[i][j][t] = 0.f;

    auto load_stage = [&](int chunk, int slot) {
        const int ph = chunk / kc;
        const int kk = (chunk - ph * kc) * 64;
        const int acol = kk + ((ph == 2) ? Kseg : 0);
        const int bcol = kk + ((ph == 1) ? Kseg : 0);
        const uint32_t sa = sbase + slot * ST_BYTES;
        const uint32_t sbB = sa + 16384;
#pragma unroll
        for (int i = 0; i < 4; i++) {
            int c = tid + 256 * i;
            int row = c >> 3, c16 = c & 7;
            cp16(sa + row * 128 + ((c16 ^ (row & 7)) << 4),
                 A + (size_t)(m0 + row) * lda + acol + c16 * 8);
        }
#pragma unroll
        for (int i = 0; i < 4; i++) {
            int c = tid + 256 * i;
            int row = c >> 3, c16 = c & 7;
            cp16(sbB + row * 128 + ((c16 ^ (row & 7)) << 4),
                 B + (size_t)(brow0 + row) * ldb + bcol + c16 * 8);
        }
        asm volatile("cp.async.commit_group;" ::: "memory");
    };

    auto compute = [&](int slot) {
        const uint32_t sa = sbase + slot * ST_BYTES;
        const uint32_t sbB = sa + 16384;
#pragma unroll
        for (int ks = 0; ks < 4; ks++) {
            uint32_t afr[4][4], bfr[4][2];
#pragma unroll
            for (int mi = 0; mi < 4; mi++) {
                int row = wm + mi * 16 + (lane & 15);
                int c16 = ks * 2 + (lane >> 4);
                ldm4(afr[mi], sa + row * 128 + ((c16 ^ (row & 7)) << 4));
            }
#pragma unroll
            for (int nj = 0; nj < 2; nj++) {
                int row = wn + nj * 16 + (lane & 7) + ((lane >> 4) & 1) * 8;
                int c16 = ks * 2 + ((lane >> 3) & 1);
                uint32_t r[4];
                ldm4(r, sbB + row * 128 + ((c16 ^ (row & 7)) << 4));
                bfr[nj * 2][0] = r[0];     bfr[nj * 2][1] = r[1];
                bfr[nj * 2 + 1][0] = r[2]; bfr[nj * 2 + 1][1] = r[3];
            }
#pragma unroll
            for (int mi = 0; mi < 4; mi++)
#pragma unroll
                for (int ni = 0; ni < 4; ni++)
                    mma16816(acc[mi][ni], afr[mi], bfr[ni]);
        }
    };

    // prologue
    load_stage(0, 0);
    load_stage(1, 1);

    for (int c = 0; c < nchunks; c++) {
        if (c + 2 < nchunks) {
            asm volatile("cp.async.wait_group 1;" ::: "memory");
        } else {
            asm volatile("cp.async.wait_group 0;" ::: "memory");
        }
        __syncthreads();
        if (c + 2 < nchunks) load_stage(c + 2, (c + 2) % 3);
        compute(c % 3);
        __syncthreads();
    }

    // ---- epilogue ----
    const int r0 = m0 + wm + (lane >> 2);
    const int cbase = n0 + wn + 2 * (lane & 3);
#pragma unroll
    for (int mi = 0; mi < 4; mi++) {
#pragma unroll
        for (int ni = 0; ni < 4; ni++) {
            int row = r0 + mi * 16;
            int col = cbase + ni * 8;
            float c0 = acc[mi][ni][0] * alpha, c1 = acc[mi][ni][1] * alpha;
            float c2 = acc[mi][ni][2] * alpha, c3 = acc[mi][ni][3] * alpha;
            if (EPI == 0) {
                *(float2*)(Cf + (size_t)row * ldc + col) = make_float2(c0, c1);
                *(float2*)(Cf + (size_t)(row + 8) * ldc + col) = make_float2(c2, c3);
            } else {
                __nv_bfloat16 h0 = __float2bfloat16(c0), h1 = __float2bfloat16(c1);
                __nv_bfloat16 h2 = __float2bfloat16(c2), h3 = __float2bfloat16(c3);
                __nv_bfloat162 hh0; hh0.x = h0; hh0.y = h1;
                __nv_bfloat162 hh1; hh1.x = h2; hh1.y = h3;
                __nv_bfloat162 ll0, ll1;
                ll0.x = __float2bfloat16(c0 - __bfloat162float(h0));
                ll0.y = __float2bfloat16(c1 - __bfloat162float(h1));
                ll1.x = __float2bfloat16(c2 - __bfloat162float(h2));
                ll1.y = __float2bfloat16(c3 - __bfloat162float(h3));
                __nv_bfloat16* hp0 = Cs + (size_t)row * (2 * ldc);
                __nv_bfloat16* hp1 = Cs + (size_t)(row + 8) * (2 * ldc);
                *(__nv_bfloat162*)(hp0 + col) = hh0;
                *(__nv_bfloat162*)(hp0 + ldc + col) = ll0;
                *(__nv_bfloat162*)(hp1 + col) = hh1;
                *(__nv_bfloat162*)(hp1 + ldc + col) = ll1;
            }
        }
    }
}

// ================== split / transpose / softmax ==================
__global__ void split_rows(const float4* __restrict__ in, __nv_bfloat16* __restrict__ out)
{
    size_t idx = (size_t)blockIdx.x * 256 + threadIdx.x;
    float4 v = in[idx];
    size_t row = idx >> 8;
    int c = (int)(idx & 255) * 4;
    __nv_bfloat16* o = out + row * 2048 + c;
    __nv_bfloat16 h0 = __float2bfloat16(v.x), h1 = __float2bfloat16(v.y);
    __nv_bfloat16 h2 = __float2bfloat16(v.z), h3 = __float2bfloat16(v.w);
    __nv_bfloat162 a, b;
    a.x = h0; a.y = h1; b.x = h2; b.y = h3;
    *(__nv_bfloat162*)(o) = a; *(__nv_bfloat162*)(o + 2) = b;
    a.x = __float2bfloat16(v.x - __bfloat162float(h0));
    a.y = __float2bfloat16(v.y - __bfloat162float(h1));
    b.x = __float2bfloat16(v.z - __bfloat162float(h2));
    b.y = __float2bfloat16(v.w - __bfloat162float(h3));
    *(__nv_bfloat162*)(o + 1024) = a; *(__nv_bfloat162*)(o + 1026) = b;
}

__global__ void transpose_split(const float* __restrict__ in, __nv_bfloat16* __restrict__ out,
                                int rows, int cols)
{
    __shared__ float t[32][33];
    const int c0 = blockIdx.x * 32, r0 = blockIdx.y * 32;
    const float* ib = in + (size_t)blockIdx.z * rows * cols;
    __nv_bfloat16* ob = out + (size_t)blockIdx.z * cols * 2 * rows;
    const int tx = threadIdx.x, ty = threadIdx.y;
#pragma unroll
    for (int i = 0; i < 4; i++)
        t[ty + 8 * i][tx] = ib[(size_t)(r0 + ty + 8 * i) * cols + c0 + tx];
    __syncthreads();
#pragma unroll
    for (int i = 0; i < 4; i++) {
        float v = t[tx][ty + 8 * i];
        __nv_bfloat16 h = __float2bfloat16(v);
        __nv_bfloat16 l = __float2bfloat16(v - __bfloat162float(h));
        size_t orow = (size_t)(c0 + ty + 8 * i) * 2 * rows;
        ob[orow + r0 + tx] = h;
        ob[orow + rows + r0 + tx] = l;
    }
}

__global__ void __launch_bounds__(256) softmax_split(const float* __restrict__ P,
                                                     __nv_bfloat16* __restrict__ Ps)
{
    const float* row = P + (size_t)blockIdx.x * 2048;
    __nv_bfloat16* orow = Ps + (size_t)blockIdx.x * 4096;
    const int tid = threadIdx.x;
    __shared__ float red[32];
    __shared__ float bcast;

    float v[8];
#pragma unroll
    for (int i = 0; i < 8; i++) v[i] = row[tid + 256 * i];

    float mx = v[0];
#pragma unroll
    for (int i = 1; i < 8; i++) mx = fmaxf(mx, v[i]);
#pragma unroll
    for (int o = 16; o; o >>= 1) mx = fmaxf(mx, __shfl_xor_sync(~0u, mx, o));
    if ((tid & 31) == 0) red[tid >> 5] = mx;
    __syncthreads();
    if (tid < 32) {
        float t = (tid < 8) ? red[tid] : -3.4e38f;
#pragma unroll
        for (int o = 4; o; o >>= 1) t = fmaxf(t, __shfl_xor_sync(~0u, t, o));
        if (tid == 0) bcast = t;
    }
    __syncthreads();
    mx = bcast;

    float sum = 0.f;
#pragma unroll
    for (int i = 0; i < 8; i++) { v[i] = __expf(v[i] - mx); sum += v[i]; }
#pragma unroll
    for (int o = 16; o; o >>= 1) sum += __shfl_xor_sync(~0u, sum, o);
    __syncthreads();
    if ((tid & 31) == 0) red[tid >> 5] = sum;
    __syncthreads();
    if (tid < 32) {
        float t = (tid < 8) ? red[tid] : 0.f;
#pragma unroll
        for (int o = 4; o; o >>= 1) t += __shfl_xor_sync(~0u, t, o);
        if (tid == 0) bcast = t;
    }
    __syncthreads();

    float inv = 1.0f / bcast;
#pragma unroll
    for (int i = 0; i < 8; i++) {
        float p = v[i] * inv;
        __nv_bfloat16 h = __float2bfloat16(p);
        __nv_bfloat16 l = __float2bfloat16(p - __bfloat162float(h));
        orow[tid + 256 * i] = h;
        orow[2048 + tid + 256 * i] = l;
    }
}

// ======================= host side =======================
extern "C" void kernel_launch(void* const* d_in, const int* in_sizes, int n_in,
                              void* d_out, int out_size)
{
    const float* X  = (const float*)d_in[0];
    const float* Wq = (const float*)d_in[1];
    const float* Wk = (const float*)d_in[2];
    const float* Wv = (const float*)d_in[3];
    float* out = (float*)d_out;

    void *xs, *wqs, *wks, *wvs, *qs, *ks, *vf, *vts, *pp, *ps;
    cudaGetSymbolAddress(&xs,  g_Xs);  cudaGetSymbolAddress(&wqs, g_Wqs);
    cudaGetSymbolAddress(&wks, g_Wks); cudaGetSymbolAddress(&wvs, g_Wvs);
    cudaGetSymbolAddress(&qs,  g_Qs);  cudaGetSymbolAddress(&ks,  g_Ks);
    cudaGetSymbolAddress(&vf,  g_Vf);  cudaGetSymbolAddress(&vts, g_Vts);
    cudaGetSymbolAddress(&pp,  g_P);   cudaGetSymbolAddress(&ps,  g_Ps);

    static bool attr_done = false;
    if (!attr_done) {
        cudaFuncSetAttribute(gemm_hmma<0>, cudaFuncAttributeMaxDynamicSharedMemorySize, SMEM_SZ);
        cudaFuncSetAttribute(gemm_hmma<1>, cudaFuncAttributeMaxDynamicSharedMemorySize, SMEM_SZ);
        attr_done = true;
    }

    // 1) split inputs
    split_rows<<<MR, 256>>>((const float4*)X, (__nv_bfloat16*)xs);
    transpose_split<<<dim3(32, 32, 1), dim3(32, 8)>>>(Wq, (__nv_bfloat16*)wqs, 1024, 1024);
    transpose_split<<<dim3(32, 32, 1), dim3(32, 8)>>>(Wk, (__nv_bfloat16*)wks, 1024, 1024);
    transpose_split<<<dim3(32, 32, 1), dim3(32, 8)>>>(Wv, (__nv_bfloat16*)wvs, 1024, 1024);

    // 2) projections: [16384,1024] = Xs * Wts^T, K' = 3*1024 -> 48 chunks
    gemm_hmma<1><<<dim3(8, 128), 256, SMEM_SZ>>>(
        (const __nv_bfloat16*)xs, (const __nv_bfloat16*)wqs, nullptr, (__nv_bfloat16*)qs,
        2048, 2048, 1024, 1024, 16, 48, 1.0f, 1 << 30, 0);
    gemm_hmma<1><<<dim3(8, 128), 256, SMEM_SZ>>>(
        (const __nv_bfloat16*)xs, (const __nv_bfloat16*)wks, nullptr, (__nv_bfloat16*)ks,
        2048, 2048, 1024, 1024, 16, 48, 1.0f, 1 << 30, 0);
    gemm_hmma<0><<<dim3(8, 128), 256, SMEM_SZ>>>(
        (const __nv_bfloat16*)xs, (const __nv_bfloat16*)wvs, (float*)vf, nullptr,
        2048, 2048, 1024, 1024, 16, 48, 1.0f, 1 << 30, 0);

    // 3) V transpose-split: V[b][s][u] -> Vts[b][u][s hi|lo]
    transpose_split<<<dim3(32, 64, 8), dim3(32, 8)>>>((const float*)vf, (__nv_bfloat16*)vts,
                                                      2048, 1024);

    // 4) scores: P = Qs * Ks^T / 32 (batched via brow0)
    gemm_hmma<0><<<dim3(16, 128), 256, SMEM_SZ>>>(
        (const __nv_bfloat16*)qs, (const __nv_bfloat16*)ks, (float*)pp, nullptr,
        2048, 2048, 2048, 1024, 16, 48, 1.0f / 32.0f, 2048, 2048);

    // 5) softmax + split -> Ps
    softmax_split<<<MR, 256>>>((const float*)pp, (__nv_bfloat16*)ps);

    // 6) out = P @ V, K' = 3*2048 -> 96 chunks
    gemm_hmma<0><<<dim3(8, 128), 256, SMEM_SZ>>>(
        (const __nv_bfloat16*)ps, (const __nv_bfloat16*)vts, out, nullptr,
        4096, 4096, 1024, 2048, 32, 96, 1.0f, 2048, 1024);
}

// round 4
// speedup vs baseline: 2.7739x; 1.2641x over previous
#include <cuda_runtime.h>
#include <cuda_bf16.h>
#include <cstdint>

// ============================================================
// B=8, S=2048, D=1024, U=1024 fp32 self-attention.
// Error-compensated bf16 split (hi+lo), 3-phase K concat:
//   a*b ~= a_hi*b_hi + a_hi*b_lo + a_lo*b_hi, K' = 3K.
// GEMM core: mma.sync m16n8k16 + cp.async 3-stage pipeline.
// R4: 4 warps/CTA, 64x64 warp tiles, 2 CTAs/SM.
// ============================================================

constexpr int CB = 8, CS = 2048;
constexpr int MR = CB * CS;   // 16384 rows, batch folded

// -------- scratch (__device__ globals; no allocation allowed) --------
__device__ __align__(1024) __nv_bfloat16 g_Xs [(size_t)MR * 2048];
__device__ __align__(1024) __nv_bfloat16 g_Wqs[(size_t)1024 * 2048];
__device__ __align__(1024) __nv_bfloat16 g_Wks[(size_t)1024 * 2048];
__device__ __align__(1024) __nv_bfloat16 g_Wvs[(size_t)1024 * 2048];
__device__ __align__(1024) __nv_bfloat16 g_Qs [(size_t)MR * 2048];
__device__ __align__(1024) __nv_bfloat16 g_Ks [(size_t)MR * 2048];
__device__ __align__(1024) float         g_Vf [(size_t)MR * 1024];
__device__ __align__(1024) __nv_bfloat16 g_Vts[(size_t)CB * 1024 * 4096];
__device__ __align__(1024) float         g_P  [(size_t)MR * 2048];
__device__ __align__(1024) __nv_bfloat16 g_Ps [(size_t)MR * 4096];

// ======================= asm helpers (sm_80-level) =======================
__device__ __forceinline__ uint32_t smem_u32(const void* p) {
    uint32_t a;
    asm("{ .reg .u64 t; cvta.to.shared.u64 t, %1; cvt.u32.u64 %0, t; }"
        : "=r"(a) : "l"(p));
    return a;
}
__device__ __forceinline__ void cp16(uint32_t sp, const void* gp) {
    asm volatile("cp.async.cg.shared.global [%0], [%1], 16;"
                 :: "r"(sp), "l"(gp) : "memory");
}
__device__ __forceinline__ void ldm4(uint32_t* r, uint32_t a) {
    asm volatile("ldmatrix.sync.aligned.m8n8.x4.shared.b16 {%0,%1,%2,%3}, [%4];"
                 : "=r"(r[0]), "=r"(r[1]), "=r"(r[2]), "=r"(r[3]) : "r"(a));
}
__device__ __forceinline__ void mma16816(float* c, const uint32_t* a, const uint32_t* b) {
    asm volatile(
        "mma.sync.aligned.m16n8k16.row.col.f32.bf16.bf16.f32 "
        "{%0,%1,%2,%3},{%4,%5,%6,%7},{%8,%9},{%0,%1,%2,%3};"
        : "+f"(c[0]), "+f"(c[1]), "+f"(c[2]), "+f"(c[3])
        : "r"(a[0]), "r"(a[1]), "r"(a[2]), "r"(a[3]), "r"(b[0]), "r"(b[1]));
}

// ======================= GEMM kernel =======================
// C[128,128] tile of C = A[M,K'] * B[N,K']^T, A/B bf16 K-major.
// K' = 3 phases over segments of width Kseg (kc = Kseg/64 chunks/phase):
//   A col offset: phase2 -> +Kseg (lo);  B col offset: phase1 -> +Kseg (lo).
// 3-stage cp.async pipeline, BK=64 (128B smem rows, xor-swizzled).
// 128 threads = 4 warps in 2x2, warp tile 64x64; 2 CTAs/SM.
constexpr int ST_BYTES = 128 * 128 * 2;        // 32KB/stage (A 16K + B 16K)
constexpr int SMEM_SZ  = 3 * ST_BYTES;         // 96KB

template <int EPI>   // 0: fp32 out (alpha), 1: split bf16 hi|lo out
__global__ void __launch_bounds__(128, 2) gemm_hmma(
    const __nv_bfloat16* __restrict__ A, const __nv_bfloat16* __restrict__ B,
    float* __restrict__ Cf, __nv_bfloat16* __restrict__ Cs,
    int lda, int ldb, int ldc, int Kseg, int kc, int nchunks,
    float alpha, int m_per_batch, int nb_rows)
{
    extern __shared__ __align__(1024) char smem[];
    const uint32_t sbase = smem_u32(smem);
    const int tid = threadIdx.x, wid = tid >> 5, lane = tid & 31;
    const int m0 = blockIdx.y * 128;
    const int n0 = blockIdx.x * 128;
    const int batch = m0 / m_per_batch;
    const int brow0 = batch * nb_rows + n0;

    const int wm = (wid & 1) * 64;   // warp M offset (2 x 64)
    const int wn = (wid >> 1) * 64;  // warp N offset (2 x 64)

    float acc[4][8][4];
#pragma unroll
    for (int i = 0; i < 4; i++)
#pragma unroll
        for (int j = 0; j < 8; j++)
#pragma unroll
            for (int t = 0; t < 4; t++) acc[i][j][t] = 0.f;

    auto load_stage = [&](int chunk, int slot) {
        const int ph = chunk / kc;
        const int kk = (chunk - ph * kc) * 64;
        const int acol = kk + ((ph == 2) ? Kseg : 0);
        const int bcol = kk + ((ph == 1) ? Kseg : 0);
        const uint32_t sa = sbase + slot * ST_BYTES;
        const uint32_t sbB = sa + 16384;
#pragma unroll
        for (int i = 0; i < 8; i++) {
            int c = tid + 128 * i;
            int row = c >> 3, c16 = c & 7;
            cp16(sa + row * 128 + ((c16 ^ (row & 7)) << 4),
                 A + (size_t)(m0 + row) * lda + acol + c16 * 8);
        }
#pragma unroll
        for (int i = 0; i < 8; i++) {
            int c = tid + 128 * i;
            int row = c >> 3, c16 = c & 7;
            cp16(sbB + row * 128 + ((c16 ^ (row & 7)) << 4),
                 B + (size_t)(brow0 + row) * ldb + bcol + c16 * 8);
        }
        asm volatile("cp.async.commit_group;" ::: "memory");
    };

    auto compute = [&](int slot) {
        const uint32_t sa = sbase + slot * ST_BYTES;
        const uint32_t sbB = sa + 16384;
#pragma unroll
        for (int ks = 0; ks < 4; ks++) {
            uint32_t afr[4][4], bfr[8][2];
#pragma unroll
            for (int mi = 0; mi < 4; mi++) {
                int row = wm + mi * 16 + (lane & 15);
                int c16 = ks * 2 + (lane >> 4);
                ldm4(afr[mi], sa + row * 128 + ((c16 ^ (row & 7)) << 4));
            }
#pragma unroll
            for (int nj = 0; nj < 4; nj++) {
                int row = wn + nj * 16 + (lane & 7) + ((lane >> 4) & 1) * 8;
                int c16 = ks * 2 + ((lane >> 3) & 1);
                uint32_t r[4];
                ldm4(r, sbB + row * 128 + ((c16 ^ (row & 7)) << 4));
                bfr[nj * 2][0] = r[0];     bfr[nj * 2][1] = r[1];
                bfr[nj * 2 + 1][0] = r[2]; bfr[nj * 2 + 1][1] = r[3];
            }
#pragma unroll
            for (int mi = 0; mi < 4; mi++)
#pragma unroll
                for (int ni = 0; ni < 8; ni++)
                    mma16816(acc[mi][ni], afr[mi], bfr[ni]);
        }
    };

    // prologue
    load_stage(0, 0);
    load_stage(1, 1);

    for (int c = 0; c < nchunks; c++) {
        if (c + 2 < nchunks) {
            asm volatile("cp.async.wait_group 1;" ::: "memory");
        } else {
            asm volatile("cp.async.wait_group 0;" ::: "memory");
        }
        __syncthreads();
        if (c + 2 < nchunks) load_stage(c + 2, (c + 2) % 3);
        compute(c % 3);
        __syncthreads();
    }

    // ---- epilogue ----
    const int r0 = m0 + wm + (lane >> 2);
    const int cbase = n0 + wn + 2 * (lane & 3);
#pragma unroll
    for (int mi = 0; mi < 4; mi++) {
#pragma unroll
        for (int ni = 0; ni < 8; ni++) {
            int row = r0 + mi * 16;
            int col = cbase + ni * 8;
            float c0 = acc[mi][ni][0] * alpha, c1 = acc[mi][ni][1] * alpha;
            float c2 = acc[mi][ni][2] * alpha, c3 = acc[mi][ni][3] * alpha;
            if (EPI == 0) {
                *(float2*)(Cf + (size_t)row * ldc + col) = make_float2(c0, c1);
                *(float2*)(Cf + (size_t)(row + 8) * ldc + col) = make_float2(c2, c3);
            } else {
                __nv_bfloat16 h0 = __float2bfloat16(c0), h1 = __float2bfloat16(c1);
                __nv_bfloat16 h2 = __float2bfloat16(c2), h3 = __float2bfloat16(c3);
                __nv_bfloat162 hh0; hh0.x = h0; hh0.y = h1;
                __nv_bfloat162 hh1; hh1.x = h2; hh1.y = h3;
                __nv_bfloat162 ll0, ll1;
                ll0.x = __float2bfloat16(c0 - __bfloat162float(h0));
                ll0.y = __float2bfloat16(c1 - __bfloat162float(h1));
                ll1.x = __float2bfloat16(c2 - __bfloat162float(h2));
                ll1.y = __float2bfloat16(c3 - __bfloat162float(h3));
                __nv_bfloat16* hp0 = Cs + (size_t)row * (2 * ldc);
                __nv_bfloat16* hp1 = Cs + (size_t)(row + 8) * (2 * ldc);
                *(__nv_bfloat162*)(hp0 + col) = hh0;
                *(__nv_bfloat162*)(hp0 + ldc + col) = ll0;
                *(__nv_bfloat162*)(hp1 + col) = hh1;
                *(__nv_bfloat162*)(hp1 + ldc + col) = ll1;
            }
        }
    }
}

// ================== split / transpose / softmax ==================
__global__ void split_rows(const float4* __restrict__ in, __nv_bfloat16* __restrict__ out)
{
    size_t idx = (size_t)blockIdx.x * 256 + threadIdx.x;
    float4 v = in[idx];
    size_t row = idx >> 8;
    int c = (int)(idx & 255) * 4;
    __nv_bfloat16* o = out + row * 2048 + c;
    __nv_bfloat16 h0 = __float2bfloat16(v.x), h1 = __float2bfloat16(v.y);
    __nv_bfloat16 h2 = __float2bfloat16(v.z), h3 = __float2bfloat16(v.w);
    __nv_bfloat162 a, b;
    a.x = h0; a.y = h1; b.x = h2; b.y = h3;
    *(__nv_bfloat162*)(o) = a; *(__nv_bfloat162*)(o + 2) = b;
    a.x = __float2bfloat16(v.x - __bfloat162float(h0));
    a.y = __float2bfloat16(v.y - __bfloat162float(h1));
    b.x = __float2bfloat16(v.z - __bfloat162float(h2));
    b.y = __float2bfloat16(v.w - __bfloat162float(h3));
    *(__nv_bfloat162*)(o + 1024) = a; *(__nv_bfloat162*)(o + 1026) = b;
}

__global__ void transpose_split(const float* __restrict__ in, __nv_bfloat16* __restrict__ out,
                                int rows, int cols)
{
    __shared__ float t[32][33];
    const int c0 = blockIdx.x * 32, r0 = blockIdx.y * 32;
    const float* ib = in + (size_t)blockIdx.z * rows * cols;
    __nv_bfloat16* ob = out + (size_t)blockIdx.z * cols * 2 * rows;
    const int tx = threadIdx.x, ty = threadIdx.y;
#pragma unroll
    for (int i = 0; i < 4; i++)
        t[ty + 8 * i][tx] = ib[(size_t)(r0 + ty + 8 * i) * cols + c0 + tx];
    __syncthreads();
#pragma unroll
    for (int i = 0; i < 4; i++) {
        float v = t[tx][ty + 8 * i];
        __nv_bfloat16 h = __float2bfloat16(v);
        __nv_bfloat16 l = __float2bfloat16(v - __bfloat162float(h));
        size_t orow = (size_t)(c0 + ty + 8 * i) * 2 * rows;
        ob[orow + r0 + tx] = h;
        ob[orow + rows + r0 + tx] = l;
    }
}

__global__ void __launch_bounds__(256) softmax_split(const float* __restrict__ P,
                                                     __nv_bfloat16* __restrict__ Ps)
{
    const float* row = P + (size_t)blockIdx.x * 2048;
    __nv_bfloat16* orow = Ps + (size_t)blockIdx.x * 4096;
    const int tid = threadIdx.x;
    __shared__ float red[32];
    __shared__ float bcast;

    float v[8];
#pragma unroll
    for (int i = 0; i < 8; i++) v[i] = row[tid + 256 * i];

    float mx = v[0];
#pragma unroll
    for (int i = 1; i < 8; i++) mx = fmaxf(mx, v[i]);
#pragma unroll
    for (int o = 16; o; o >>= 1) mx = fmaxf(mx, __shfl_xor_sync(~0u, mx, o));
    if ((tid & 31) == 0) red[tid >> 5] = mx;
    __syncthreads();
    if (tid < 32) {
        float t = (tid < 8) ? red[tid] : -3.4e38f;
#pragma unroll
        for (int o = 4; o; o >>= 1) t = fmaxf(t, __shfl_xor_sync(~0u, t, o));
        if (tid == 0) bcast = t;
    }
    __syncthreads();
    mx = bcast;

    float sum = 0.f;
#pragma unroll
    for (int i = 0; i < 8; i++) { v[i] = __expf(v[i] - mx); sum += v[i]; }
#pragma unroll
    for (int o = 16; o; o >>= 1) sum += __shfl_xor_sync(~0u, sum, o);
    __syncthreads();
    if ((tid & 31) == 0) red[tid >> 5] = sum;
    __syncthreads();
    if (tid < 32) {
        float t = (tid < 8) ? red[tid] : 0.f;
#pragma unroll
        for (int o = 4; o; o >>= 1) t += __shfl_xor_sync(~0u, t, o);
        if (tid == 0) bcast = t;
    }
    __syncthreads();

    float inv = 1.0f / bcast;
#pragma unroll
    for (int i = 0; i < 8; i++) {
        float p = v[i] * inv;
        __nv_bfloat16 h = __float2bfloat16(p);
        __nv_bfloat16 l = __float2bfloat16(p - __bfloat162float(h));
        orow[tid + 256 * i] = h;
        orow[2048 + tid + 256 * i] = l;
    }
}

// ======================= host side =======================
extern "C" void kernel_launch(void* const* d_in, const int* in_sizes, int n_in,
                              void* d_out, int out_size)
{
    const float* X  = (const float*)d_in[0];
    const float* Wq = (const float*)d_in[1];
    const float* Wk = (const float*)d_in[2];
    const float* Wv = (const float*)d_in[3];
    float* out = (float*)d_out;

    void *xs, *wqs, *wks, *wvs, *qs, *ks, *vf, *vts, *pp, *ps;
    cudaGetSymbolAddress(&xs,  g_Xs);  cudaGetSymbolAddress(&wqs, g_Wqs);
    cudaGetSymbolAddress(&wks, g_Wks); cudaGetSymbolAddress(&wvs, g_Wvs);
    cudaGetSymbolAddress(&qs,  g_Qs);  cudaGetSymbolAddress(&ks,  g_Ks);
    cudaGetSymbolAddress(&vf,  g_Vf);  cudaGetSymbolAddress(&vts, g_Vts);
    cudaGetSymbolAddress(&pp,  g_P);   cudaGetSymbolAddress(&ps,  g_Ps);

    static bool attr_done = false;
    if (!attr_done) {
        cudaFuncSetAttribute(gemm_hmma<0>, cudaFuncAttributeMaxDynamicSharedMemorySize, SMEM_SZ);
        cudaFuncSetAttribute(gemm_hmma<1>, cudaFuncAttributeMaxDynamicSharedMemorySize, SMEM_SZ);
        attr_done = true;
    }

    // 1) split inputs
    split_rows<<<MR, 256>>>((const float4*)X, (__nv_bfloat16*)xs);
    transpose_split<<<dim3(32, 32, 1), dim3(32, 8)>>>(Wq, (__nv_bfloat16*)wqs, 1024, 1024);
    transpose_split<<<dim3(32, 32, 1), dim3(32, 8)>>>(Wk, (__nv_bfloat16*)wks, 1024, 1024);
    transpose_split<<<dim3(32, 32, 1), dim3(32, 8)>>>(Wv, (__nv_bfloat16*)wvs, 1024, 1024);

    // 2) projections: [16384,1024] = Xs * Wts^T, K' = 3*1024 -> 48 chunks
    gemm_hmma<1><<<dim3(8, 128), 128, SMEM_SZ>>>(
        (const __nv_bfloat16*)xs, (const __nv_bfloat16*)wqs, nullptr, (__nv_bfloat16*)qs,
        2048, 2048, 1024, 1024, 16, 48, 1.0f, 1 << 30, 0);
    gemm_hmma<1><<<dim3(8, 128), 128, SMEM_SZ>>>(
        (const __nv_bfloat16*)xs, (const __nv_bfloat16*)wks, nullptr, (__nv_bfloat16*)ks,
        2048, 2048, 1024, 1024, 16, 48, 1.0f, 1 << 30, 0);
    gemm_hmma<0><<<dim3(8, 128), 128, SMEM_SZ>>>(
        (const __nv_bfloat16*)xs, (const __nv_bfloat16*)wvs, (float*)vf, nullptr,
        2048, 2048, 1024, 1024, 16, 48, 1.0f, 1 << 30, 0);

    // 3) V transpose-split: V[b][s][u] -> Vts[b][u][s hi|lo]
    transpose_split<<<dim3(32, 64, 8), dim3(32, 8)>>>((const float*)vf, (__nv_bfloat16*)vts,
                                                      2048, 1024);

    // 4) scores: P = Qs * Ks^T / 32 (batched via brow0)
    gemm_hmma<0><<<dim3(16, 128), 128, SMEM_SZ>>>(
        (const __nv_bfloat16*)qs, (const __nv_bfloat16*)ks, (float*)pp, nullptr,
        2048, 2048, 2048, 1024, 16, 48, 1.0f / 32.0f, 2048, 2048);

    // 5) softmax + split -> Ps
    softmax_split<<<MR, 256>>>((const float*)pp, (__nv_bfloat16*)ps);

    // 6) out = P @ V, K' = 3*2048 -> 96 chunks
    gemm_hmma<0><<<dim3(8, 128), 128, SMEM_SZ>>>(
        (const __nv_bfloat16*)ps, (const __nv_bfloat16*)vts, out, nullptr,
        4096, 4096, 1024, 2048, 32, 96, 1.0f, 2048, 1024);
}